// round 1
// baseline (speedup 1.0000x reference)
#include <cuda_runtime.h>
#include <mma.h>

using namespace nvcuda;

#define NN 8192
#define CC 256

// scratch (allocation-free rule: __device__ globals)
__device__ float g_s[NN];            // d^{-1/2}
__device__ float g_t[NN * CC];       // t = adj @ (s .* x)

// ---------------------------------------------------------------------------
// Kernel 1: s[i] = rsqrt(1 + sum_j adj[i][j])   (A = adj + I -> rowsum + 1)
// one warp per row, 8 rows per block
// ---------------------------------------------------------------------------
__global__ void rowsum_kernel(const float* __restrict__ adj) {
    int row = blockIdx.x * blockDim.y + threadIdx.y;
    const float4* p = reinterpret_cast<const float4*>(adj + (size_t)row * NN);
    float sum = 0.0f;
#pragma unroll 4
    for (int i = threadIdx.x; i < NN / 4; i += 32) {
        float4 v = p[i];
        sum += (v.x + v.y) + (v.z + v.w);
    }
#pragma unroll
    for (int o = 16; o > 0; o >>= 1) sum += __shfl_xor_sync(0xffffffffu, sum, o);
    if (threadIdx.x == 0) g_s[row] = rsqrtf(sum + 1.0f);
}

// ---------------------------------------------------------------------------
// Shared GEMM tiling constants (tf32 WMMA 16x16x8)
// Block tile 128x128, BK=16, 256 threads = 8 warps in 4(M) x 2(N),
// warp tile 32x64 = 2x4 wmma fragments.
// ---------------------------------------------------------------------------
constexpr int BM = 128;
constexpr int BN = 128;
constexpr int BK = 16;
constexpr int AKP = BK + 4;   // 20 (pad; multiple of 4 for wmma ldm)
constexpr int BNP = BN + 4;   // 132

// ---------------------------------------------------------------------------
// Kernel 2: t = adj @ (s .* x)      (tf32 tensor cores, fp32 accumulate)
// ---------------------------------------------------------------------------
__global__ __launch_bounds__(256, 1)
void gemm1_kernel(const float* __restrict__ adj, const float* __restrict__ x) {
    __shared__ float As[2][BM * AKP];
    __shared__ float Bs[2][BK * BNP];

    const int tid  = threadIdx.x;
    const int warp = tid >> 5;
    const int wm   = warp & 3;   // 0..3 along M (32 rows)
    const int wn   = warp >> 2;  // 0..1 along N (64 cols)
    const int m0   = blockIdx.y * BM;
    const int n0   = blockIdx.x * BN;

    // load index precompute: A tile = 512 float4, B tile = 512 float4, 2/thread
    const int aE0 = tid, aE1 = tid + 256;
    const int aR0 = aE0 >> 2, aC0 = (aE0 & 3) * 4;
    const int aR1 = aE1 >> 2, aC1 = (aE1 & 3) * 4;
    const int bR0 = aE0 >> 5, bC0 = (aE0 & 31) * 4;
    const int bR1 = aE1 >> 5, bC1 = (aE1 & 31) * 4;

    wmma::fragment<wmma::accumulator, 16, 16, 8, float> acc[2][4];
#pragma unroll
    for (int i = 0; i < 2; i++)
#pragma unroll
        for (int j = 0; j < 4; j++) wmma::fill_fragment(acc[i][j], 0.0f);

    float4 ra0, ra1, rb0, rb1;
    float sb0, sb1;

    // prologue: load tile 0
    {
        ra0 = *reinterpret_cast<const float4*>(adj + (size_t)(m0 + aR0) * NN + aC0);
        ra1 = *reinterpret_cast<const float4*>(adj + (size_t)(m0 + aR1) * NN + aC1);
        rb0 = *reinterpret_cast<const float4*>(x + (size_t)bR0 * CC + n0 + bC0);
        rb1 = *reinterpret_cast<const float4*>(x + (size_t)bR1 * CC + n0 + bC1);
        sb0 = g_s[bR0];
        sb1 = g_s[bR1];
        float* d;
        d = &As[0][aR0 * AKP + aC0];
        d[0] = wmma::__float_to_tf32(ra0.x); d[1] = wmma::__float_to_tf32(ra0.y);
        d[2] = wmma::__float_to_tf32(ra0.z); d[3] = wmma::__float_to_tf32(ra0.w);
        d = &As[0][aR1 * AKP + aC1];
        d[0] = wmma::__float_to_tf32(ra1.x); d[1] = wmma::__float_to_tf32(ra1.y);
        d[2] = wmma::__float_to_tf32(ra1.z); d[3] = wmma::__float_to_tf32(ra1.w);
        d = &Bs[0][bR0 * BNP + bC0];
        d[0] = wmma::__float_to_tf32(sb0 * rb0.x); d[1] = wmma::__float_to_tf32(sb0 * rb0.y);
        d[2] = wmma::__float_to_tf32(sb0 * rb0.z); d[3] = wmma::__float_to_tf32(sb0 * rb0.w);
        d = &Bs[0][bR1 * BNP + bC1];
        d[0] = wmma::__float_to_tf32(sb1 * rb1.x); d[1] = wmma::__float_to_tf32(sb1 * rb1.y);
        d[2] = wmma::__float_to_tf32(sb1 * rb1.z); d[3] = wmma::__float_to_tf32(sb1 * rb1.w);
    }
    __syncthreads();

    const int nkt = NN / BK;  // 512
    for (int kt = 0; kt < nkt; kt++) {
        const int cur = kt & 1;
        const int nxt = cur ^ 1;
        if (kt + 1 < nkt) {
            const int k = (kt + 1) * BK;
            ra0 = *reinterpret_cast<const float4*>(adj + (size_t)(m0 + aR0) * NN + k + aC0);
            ra1 = *reinterpret_cast<const float4*>(adj + (size_t)(m0 + aR1) * NN + k + aC1);
            rb0 = *reinterpret_cast<const float4*>(x + (size_t)(k + bR0) * CC + n0 + bC0);
            rb1 = *reinterpret_cast<const float4*>(x + (size_t)(k + bR1) * CC + n0 + bC1);
            sb0 = g_s[k + bR0];
            sb1 = g_s[k + bR1];
        }
#pragma unroll
        for (int ks = 0; ks < 2; ks++) {
            wmma::fragment<wmma::matrix_a, 16, 16, 8, wmma::precision::tf32, wmma::row_major> af[2];
            wmma::fragment<wmma::matrix_b, 16, 16, 8, wmma::precision::tf32, wmma::row_major> bf[4];
#pragma unroll
            for (int i = 0; i < 2; i++)
                wmma::load_matrix_sync(af[i], &As[cur][(wm * 32 + i * 16) * AKP + ks * 8], AKP);
#pragma unroll
            for (int j = 0; j < 4; j++)
                wmma::load_matrix_sync(bf[j], &Bs[cur][(ks * 8) * BNP + wn * 64 + j * 16], BNP);
#pragma unroll
            for (int i = 0; i < 2; i++)
#pragma unroll
                for (int j = 0; j < 4; j++)
                    wmma::mma_sync(acc[i][j], af[i], bf[j], acc[i][j]);
        }
        if (kt + 1 < nkt) {
            float* d;
            d = &As[nxt][aR0 * AKP + aC0];
            d[0] = wmma::__float_to_tf32(ra0.x); d[1] = wmma::__float_to_tf32(ra0.y);
            d[2] = wmma::__float_to_tf32(ra0.z); d[3] = wmma::__float_to_tf32(ra0.w);
            d = &As[nxt][aR1 * AKP + aC1];
            d[0] = wmma::__float_to_tf32(ra1.x); d[1] = wmma::__float_to_tf32(ra1.y);
            d[2] = wmma::__float_to_tf32(ra1.z); d[3] = wmma::__float_to_tf32(ra1.w);
            d = &Bs[nxt][bR0 * BNP + bC0];
            d[0] = wmma::__float_to_tf32(sb0 * rb0.x); d[1] = wmma::__float_to_tf32(sb0 * rb0.y);
            d[2] = wmma::__float_to_tf32(sb0 * rb0.z); d[3] = wmma::__float_to_tf32(sb0 * rb0.w);
            d = &Bs[nxt][bR1 * BNP + bC1];
            d[0] = wmma::__float_to_tf32(sb1 * rb1.x); d[1] = wmma::__float_to_tf32(sb1 * rb1.y);
            d[2] = wmma::__float_to_tf32(sb1 * rb1.z); d[3] = wmma::__float_to_tf32(sb1 * rb1.w);
            __syncthreads();
        }
    }

    // epilogue: raw t (s_i scaling deferred to gemm2's A-load)
#pragma unroll
    for (int i = 0; i < 2; i++)
#pragma unroll
        for (int j = 0; j < 4; j++) {
            int r = m0 + wm * 32 + i * 16;
            int c = n0 + wn * 64 + j * 16;
            wmma::store_matrix_sync(&g_t[(size_t)r * CC + c], acc[i][j], CC, wmma::mem_row_major);
        }
}

// ---------------------------------------------------------------------------
// Kernel 3: out = ELU( (s_i*(t + s_i*x)) @ w )
// ---------------------------------------------------------------------------
__global__ __launch_bounds__(256, 1)
void gemm2_kernel(const float* __restrict__ x, const float* __restrict__ w,
                  float* __restrict__ out) {
    __shared__ float As[2][BM * AKP];
    __shared__ float Bs[2][BK * BNP];

    const int tid  = threadIdx.x;
    const int warp = tid >> 5;
    const int wm   = warp & 3;
    const int wn   = warp >> 2;
    const int m0   = blockIdx.y * BM;
    const int n0   = blockIdx.x * BN;

    const int aE0 = tid, aE1 = tid + 256;
    const int aR0 = aE0 >> 2, aC0 = (aE0 & 3) * 4;
    const int aR1 = aE1 >> 2, aC1 = (aE1 & 3) * 4;
    const int bR0 = aE0 >> 5, bC0 = (aE0 & 31) * 4;
    const int bR1 = aE1 >> 5, bC1 = (aE1 & 31) * 4;

    const float sA0 = g_s[m0 + aR0];
    const float sA1 = g_s[m0 + aR1];

    wmma::fragment<wmma::accumulator, 16, 16, 8, float> acc[2][4];
#pragma unroll
    for (int i = 0; i < 2; i++)
#pragma unroll
        for (int j = 0; j < 4; j++) wmma::fill_fragment(acc[i][j], 0.0f);

    float4 ra0, ra1, rb0, rb1;

    auto fuseA = [&](float4 t4, float4 x4, float s) {
        float4 r;
        r.x = s * (t4.x + s * x4.x);
        r.y = s * (t4.y + s * x4.y);
        r.z = s * (t4.z + s * x4.z);
        r.w = s * (t4.w + s * x4.w);
        return r;
    };

    // prologue
    {
        float4 t0 = *reinterpret_cast<const float4*>(g_t + (size_t)(m0 + aR0) * CC + aC0);
        float4 x0 = *reinterpret_cast<const float4*>(x + (size_t)(m0 + aR0) * CC + aC0);
        float4 t1 = *reinterpret_cast<const float4*>(g_t + (size_t)(m0 + aR1) * CC + aC1);
        float4 x1 = *reinterpret_cast<const float4*>(x + (size_t)(m0 + aR1) * CC + aC1);
        ra0 = fuseA(t0, x0, sA0);
        ra1 = fuseA(t1, x1, sA1);
        rb0 = *reinterpret_cast<const float4*>(w + (size_t)bR0 * CC + n0 + bC0);
        rb1 = *reinterpret_cast<const float4*>(w + (size_t)bR1 * CC + n0 + bC1);
        float* d;
        d = &As[0][aR0 * AKP + aC0];
        d[0] = wmma::__float_to_tf32(ra0.x); d[1] = wmma::__float_to_tf32(ra0.y);
        d[2] = wmma::__float_to_tf32(ra0.z); d[3] = wmma::__float_to_tf32(ra0.w);
        d = &As[0][aR1 * AKP + aC1];
        d[0] = wmma::__float_to_tf32(ra1.x); d[1] = wmma::__float_to_tf32(ra1.y);
        d[2] = wmma::__float_to_tf32(ra1.z); d[3] = wmma::__float_to_tf32(ra1.w);
        d = &Bs[0][bR0 * BNP + bC0];
        d[0] = wmma::__float_to_tf32(rb0.x); d[1] = wmma::__float_to_tf32(rb0.y);
        d[2] = wmma::__float_to_tf32(rb0.z); d[3] = wmma::__float_to_tf32(rb0.w);
        d = &Bs[0][bR1 * BNP + bC1];
        d[0] = wmma::__float_to_tf32(rb1.x); d[1] = wmma::__float_to_tf32(rb1.y);
        d[2] = wmma::__float_to_tf32(rb1.z); d[3] = wmma::__float_to_tf32(rb1.w);
    }
    __syncthreads();

    const int nkt = CC / BK;  // 16
    for (int kt = 0; kt < nkt; kt++) {
        const int cur = kt & 1;
        const int nxt = cur ^ 1;
        if (kt + 1 < nkt) {
            const int k = (kt + 1) * BK;
            float4 t0 = *reinterpret_cast<const float4*>(g_t + (size_t)(m0 + aR0) * CC + k + aC0);
            float4 x0 = *reinterpret_cast<const float4*>(x + (size_t)(m0 + aR0) * CC + k + aC0);
            float4 t1 = *reinterpret_cast<const float4*>(g_t + (size_t)(m0 + aR1) * CC + k + aC1);
            float4 x1 = *reinterpret_cast<const float4*>(x + (size_t)(m0 + aR1) * CC + k + aC1);
            ra0 = fuseA(t0, x0, sA0);
            ra1 = fuseA(t1, x1, sA1);
            rb0 = *reinterpret_cast<const float4*>(w + (size_t)(k + bR0) * CC + n0 + bC0);
            rb1 = *reinterpret_cast<const float4*>(w + (size_t)(k + bR1) * CC + n0 + bC1);
        }
#pragma unroll
        for (int ks = 0; ks < 2; ks++) {
            wmma::fragment<wmma::matrix_a, 16, 16, 8, wmma::precision::tf32, wmma::row_major> af[2];
            wmma::fragment<wmma::matrix_b, 16, 16, 8, wmma::precision::tf32, wmma::row_major> bf[4];
#pragma unroll
            for (int i = 0; i < 2; i++)
                wmma::load_matrix_sync(af[i], &As[cur][(wm * 32 + i * 16) * AKP + ks * 8], AKP);
#pragma unroll
            for (int j = 0; j < 4; j++)
                wmma::load_matrix_sync(bf[j], &Bs[cur][(ks * 8) * BNP + wn * 64 + j * 16], BNP);
#pragma unroll
            for (int i = 0; i < 2; i++)
#pragma unroll
                for (int j = 0; j < 4; j++)
                    wmma::mma_sync(acc[i][j], af[i], bf[j], acc[i][j]);
        }
        if (kt + 1 < nkt) {
            float* d;
            d = &As[nxt][aR0 * AKP + aC0];
            d[0] = wmma::__float_to_tf32(ra0.x); d[1] = wmma::__float_to_tf32(ra0.y);
            d[2] = wmma::__float_to_tf32(ra0.z); d[3] = wmma::__float_to_tf32(ra0.w);
            d = &As[nxt][aR1 * AKP + aC1];
            d[0] = wmma::__float_to_tf32(ra1.x); d[1] = wmma::__float_to_tf32(ra1.y);
            d[2] = wmma::__float_to_tf32(ra1.z); d[3] = wmma::__float_to_tf32(ra1.w);
            d = &Bs[nxt][bR0 * BNP + bC0];
            d[0] = wmma::__float_to_tf32(rb0.x); d[1] = wmma::__float_to_tf32(rb0.y);
            d[2] = wmma::__float_to_tf32(rb0.z); d[3] = wmma::__float_to_tf32(rb0.w);
            d = &Bs[nxt][bR1 * BNP + bC1];
            d[0] = wmma::__float_to_tf32(rb1.x); d[1] = wmma::__float_to_tf32(rb1.y);
            d[2] = wmma::__float_to_tf32(rb1.z); d[3] = wmma::__float_to_tf32(rb1.w);
            __syncthreads();
        }
    }

    // epilogue: ELU on fragment elements (uniform elementwise op -> mapping-safe)
#pragma unroll
    for (int i = 0; i < 2; i++)
#pragma unroll
        for (int j = 0; j < 4; j++) {
#pragma unroll
            for (int e = 0; e < acc[i][j].num_elements; e++) {
                float v = acc[i][j].x[e];
                acc[i][j].x[e] = (v > 0.0f) ? v : expm1f(v);
            }
            int r = m0 + wm * 32 + i * 16;
            int c = n0 + wn * 64 + j * 16;
            wmma::store_matrix_sync(&out[(size_t)r * CC + c], acc[i][j], CC, wmma::mem_row_major);
        }
}

// ---------------------------------------------------------------------------
extern "C" void kernel_launch(void* const* d_in, const int* in_sizes, int n_in,
                              void* d_out, int out_size) {
    // robust input identification by element count
    const float* x = nullptr;
    const float* adj = nullptr;
    const float* w = nullptr;
    for (int i = 0; i < n_in; i++) {
        if (in_sizes[i] == NN * NN) adj = (const float*)d_in[i];
        else if (in_sizes[i] == NN * CC) x = (const float*)d_in[i];
        else if (in_sizes[i] == CC * CC) w = (const float*)d_in[i];
    }
    float* out = (float*)d_out;

    rowsum_kernel<<<NN / 8, dim3(32, 8)>>>(adj);
    // grid.x = n-tile (2) so the two col-blocks of a row-tile are adjacent ->
    // co-resident -> adj read deduped in L2
    gemm1_kernel<<<dim3(CC / BN, NN / BM), 256>>>(adj, x);
    gemm2_kernel<<<dim3(CC / BN, NN / BM), 256>>>(x, w, out);
}

// round 3
// speedup vs baseline: 4.2869x; 4.2869x over previous
#include <cuda_runtime.h>
#include <cuda_fp16.h>
#include <mma.h>
#include <cstdint>

using namespace nvcuda;

#define NN 8192
#define CC 256

// ---------------------------------------------------------------------------
// Scratch (__device__ globals; allocation-free rule)
// ---------------------------------------------------------------------------
__device__ float  g_s[NN];                       // d^{-1/2}
__device__ __half g_adjh[(size_t)NN * NN];       // fp16(adj)
__device__ __half g_xsh[NN * CC];                // fp16(s_j * x[j][n])  [K][N]
__device__ __half g_a2h[NN * CC];                // fp16(s_i*(t + s_i*x)) [M][K]
__device__ __half g_wh[CC * CC];                 // fp16(w)  [K][N]

// ---------------------------------------------------------------------------
__device__ __forceinline__ uint32_t smem_u32(const void* p) {
    uint32_t a;
    asm("{ .reg .u64 t; cvta.to.shared.u64 t, %1; cvt.u32.u64 %0, t; }" : "=r"(a) : "l"(p));
    return a;
}
__device__ __forceinline__ void cpa16(uint32_t s, const void* g) {
    asm volatile("cp.async.cg.shared.global [%0], [%1], 16;" :: "r"(s), "l"(g));
}
#define CP_COMMIT() asm volatile("cp.async.commit_group;" ::: "memory")
#define CP_WAIT_2() asm volatile("cp.async.wait_group 2;" ::: "memory")

// ---------------------------------------------------------------------------
// Kernel 1: fused rowsum + f32->fp16 convert of adj.
//   s[i] = rsqrt(1 + rowsum(adj[i,:]));  g_adjh = fp16(adj)
// one warp per row, 8 rows per block
// ---------------------------------------------------------------------------
__global__ void rowsum_convert_kernel(const float* __restrict__ adj) {
    const int row = blockIdx.x * blockDim.y + threadIdx.y;
    const float4* p = reinterpret_cast<const float4*>(adj + (size_t)row * NN);
    uint2* hout = reinterpret_cast<uint2*>(g_adjh + (size_t)row * NN);
    float sum = 0.0f;
#pragma unroll 4
    for (int i = threadIdx.x; i < NN / 4; i += 32) {
        float4 v = p[i];
        sum += (v.x + v.y) + (v.z + v.w);
        __half2 h0 = __floats2half2_rn(v.x, v.y);
        __half2 h1 = __floats2half2_rn(v.z, v.w);
        uint2 u;
        u.x = *reinterpret_cast<uint32_t*>(&h0);
        u.y = *reinterpret_cast<uint32_t*>(&h1);
        hout[i] = u;
    }
#pragma unroll
    for (int o = 16; o > 0; o >>= 1) sum += __shfl_xor_sync(0xffffffffu, sum, o);
    if (threadIdx.x == 0) g_s[row] = rsqrtf(sum + 1.0f);
}

// ---------------------------------------------------------------------------
// prep: g_xsh[j][n] = fp16(s_j * x[j][n])   (elementwise, float4-granular)
// ---------------------------------------------------------------------------
__global__ void prep_xs_kernel(const float* __restrict__ x) {
    const int idx = blockIdx.x * 256 + threadIdx.x;   // over NN*CC/4 float4s
    const int row = idx >> 6;                          // CC/4 = 64 per row
    const float s = g_s[row];
    float4 v = reinterpret_cast<const float4*>(x)[idx];
    __half2 h0 = __floats2half2_rn(s * v.x, s * v.y);
    __half2 h1 = __floats2half2_rn(s * v.z, s * v.w);
    uint2 u;
    u.x = *reinterpret_cast<uint32_t*>(&h0);
    u.y = *reinterpret_cast<uint32_t*>(&h1);
    reinterpret_cast<uint2*>(g_xsh)[idx] = u;
}

__global__ void prep_w_kernel(const float* __restrict__ w) {
    const int idx = blockIdx.x * 256 + threadIdx.x;   // over CC*CC/4 float4s
    float4 v = reinterpret_cast<const float4*>(w)[idx];
    __half2 h0 = __floats2half2_rn(v.x, v.y);
    __half2 h1 = __floats2half2_rn(v.z, v.w);
    uint2 u;
    u.x = *reinterpret_cast<uint32_t*>(&h0);
    u.y = *reinterpret_cast<uint32_t*>(&h1);
    reinterpret_cast<uint2*>(g_wh)[idx] = u;
}

// ---------------------------------------------------------------------------
// fp16 WMMA GEMM, 4-stage cp.async pipeline.
//   D[BM=128 x BN=128] += A[M,K](row-major fp16) @ B[K,N](row-major fp16)
//   MODE 0: epilogue writes g_a2h = fp16( s_i * (D + s_i * x) )
//   MODE 1: epilogue writes out  = ELU(D)  (f32)
// 256 threads = 8 warps as 4(M) x 2(N); warp tile 32x64 = 2x4 wmma 16x16x16.
// ---------------------------------------------------------------------------
constexpr int BM = 128, BN = 128, BK = 64, STAGES = 4;
constexpr int APAD = 72;                   // A smem row stride (halves)
constexpr int BPAD = 136;                  // B smem row stride (halves)
constexpr int A_HALVES = BM * APAD;        // 9216
constexpr int B_HALVES = BK * BPAD;        // 8704
constexpr int STAGE_BYTES = (A_HALVES + B_HALVES) * 2;   // 35840
constexpr int SMEM_BYTES = STAGES * STAGE_BYTES;          // 143360

template <int MODE>
__global__ __launch_bounds__(256, 1)
void gemm_fp16(const __half* __restrict__ A, const __half* __restrict__ B,
               int kA, int k_iters,
               const float* __restrict__ xin, float* __restrict__ outp) {
    extern __shared__ char smem[];
    const uint32_t sb = smem_u32(smem);
    const int tid = threadIdx.x;
    const int warp = tid >> 5;
    const int wm = warp & 3;     // 0..3 along M
    const int wn = warp >> 2;    // 0..1 along N
    const int m0 = blockIdx.y * BM;
    const int n0 = blockIdx.x * BN;

    // per-thread cp.async chunk coordinates (4 chunks for A, 4 for B)
    // A tile: 128 rows x 8 chunks(16B);  B tile: 64 rows x 16 chunks(16B)
    wmma::fragment<wmma::accumulator, 16, 16, 16, float> acc[2][4];
#pragma unroll
    for (int i = 0; i < 2; i++)
#pragma unroll
        for (int j = 0; j < 4; j++) wmma::fill_fragment(acc[i][j], 0.0f);

    auto load_stage = [&](int kt, int s) {
        const uint32_t sa = sb + s * STAGE_BYTES;
        const uint32_t sbB = sa + A_HALVES * 2;
#pragma unroll
        for (int r = 0; r < 4; r++) {
            const int c = tid + r * 256;
            const int ar = c >> 3, ac = c & 7;
            cpa16(sa + (ar * APAD + ac * 8) * 2,
                  A + (size_t)(m0 + ar) * kA + kt * BK + ac * 8);
        }
#pragma unroll
        for (int r = 0; r < 4; r++) {
            const int c = tid + r * 256;
            const int br = c >> 4, bc = c & 15;
            cpa16(sbB + (br * BPAD + bc * 8) * 2,
                  B + (size_t)(kt * BK + br) * CC + n0 + bc * 8);
        }
    };

    // prologue: stages 0..2
#pragma unroll
    for (int s = 0; s < STAGES - 1; s++) {
        if (s < k_iters) load_stage(s, s);
        CP_COMMIT();
    }

    for (int kt = 0; kt < k_iters; kt++) {
        CP_WAIT_2();
        __syncthreads();

        const int nk = kt + STAGES - 1;
        if (nk < k_iters) load_stage(nk, nk & 3);
        CP_COMMIT();   // unconditional: keeps group accounting exact in the tail

        const __half* Ap = reinterpret_cast<const __half*>(smem + (kt & 3) * STAGE_BYTES);
        const __half* Bp = Ap + A_HALVES;
#pragma unroll
        for (int ks = 0; ks < 4; ks++) {
            wmma::fragment<wmma::matrix_a, 16, 16, 16, __half, wmma::row_major> af[2];
            wmma::fragment<wmma::matrix_b, 16, 16, 16, __half, wmma::row_major> bf[4];
#pragma unroll
            for (int i = 0; i < 2; i++)
                wmma::load_matrix_sync(af[i], Ap + (wm * 32 + i * 16) * APAD + ks * 16, APAD);
#pragma unroll
            for (int j = 0; j < 4; j++)
                wmma::load_matrix_sync(bf[j], Bp + (ks * 16) * BPAD + wn * 64 + j * 16, BPAD);
#pragma unroll
            for (int i = 0; i < 2; i++)
#pragma unroll
                for (int j = 0; j < 4; j++)
                    wmma::mma_sync(acc[i][j], af[i], bf[j], acc[i][j]);
        }
        __syncthreads();
    }

    // ---- epilogue: stage accumulators to smem (f32), then fused writeback ----
    float* stg = reinterpret_cast<float*>(smem);   // 128 x 132
#pragma unroll
    for (int i = 0; i < 2; i++)
#pragma unroll
        for (int j = 0; j < 4; j++)
            wmma::store_matrix_sync(stg + (wm * 32 + i * 16) * 132 + wn * 64 + j * 16,
                                    acc[i][j], 132, wmma::mem_row_major);
    __syncthreads();

    const int r = tid >> 1;             // 0..127
    const int c0 = (tid & 1) * 64;      // 0 or 64
    const int grow = m0 + r;
    float sA = 0.0f;
    if (MODE == 0) sA = g_s[grow];
#pragma unroll
    for (int c = 0; c < 64; c += 4) {
        float4 v = *reinterpret_cast<const float4*>(stg + r * 132 + c0 + c);
        const int gcol = n0 + c0 + c;
        if (MODE == 0) {
            const float4 xv = *reinterpret_cast<const float4*>(xin + (size_t)grow * CC + gcol);
            __half2 h0 = __floats2half2_rn(sA * (v.x + sA * xv.x), sA * (v.y + sA * xv.y));
            __half2 h1 = __floats2half2_rn(sA * (v.z + sA * xv.z), sA * (v.w + sA * xv.w));
            uint2 u;
            u.x = *reinterpret_cast<uint32_t*>(&h0);
            u.y = *reinterpret_cast<uint32_t*>(&h1);
            *reinterpret_cast<uint2*>(&g_a2h[(size_t)grow * CC + gcol]) = u;
        } else {
            v.x = (v.x > 0.0f) ? v.x : expm1f(v.x);
            v.y = (v.y > 0.0f) ? v.y : expm1f(v.y);
            v.z = (v.z > 0.0f) ? v.z : expm1f(v.z);
            v.w = (v.w > 0.0f) ? v.w : expm1f(v.w);
            *reinterpret_cast<float4*>(&outp[(size_t)grow * CC + gcol]) = v;
        }
    }
}

// ---------------------------------------------------------------------------
extern "C" void kernel_launch(void* const* d_in, const int* in_sizes, int n_in,
                              void* d_out, int out_size) {
    const float *x = nullptr, *adj = nullptr, *w = nullptr;
    for (int i = 0; i < n_in; i++) {
        if (in_sizes[i] == NN * NN) adj = (const float*)d_in[i];
        else if (in_sizes[i] == NN * CC) x = (const float*)d_in[i];
        else if (in_sizes[i] == CC * CC) w = (const float*)d_in[i];
    }
    float* out = (float*)d_out;

    void *p_adjh = nullptr, *p_xsh = nullptr, *p_a2h = nullptr, *p_wh = nullptr;
    cudaGetSymbolAddress(&p_adjh, g_adjh);
    cudaGetSymbolAddress(&p_xsh, g_xsh);
    cudaGetSymbolAddress(&p_a2h, g_a2h);
    cudaGetSymbolAddress(&p_wh, g_wh);

    cudaFuncSetAttribute(gemm_fp16<0>, cudaFuncAttributeMaxDynamicSharedMemorySize, SMEM_BYTES);
    cudaFuncSetAttribute(gemm_fp16<1>, cudaFuncAttributeMaxDynamicSharedMemorySize, SMEM_BYTES);

    rowsum_convert_kernel<<<NN / 8, dim3(32, 8)>>>(adj);
    prep_xs_kernel<<<NN * CC / 4 / 256, 256>>>(x);
    prep_w_kernel<<<CC * CC / 4 / 256, 256>>>(w);
    // grid: blockIdx.x = N tile (2, fast) so the pair sharing an adj row-tile
    // is co-resident -> L2 dedups the A read.
    gemm_fp16<0><<<dim3(2, 64), 256, SMEM_BYTES>>>(
        (const __half*)p_adjh, (const __half*)p_xsh, NN, NN / BK, x, nullptr);
    gemm_fp16<1><<<dim3(2, 64), 256, SMEM_BYTES>>>(
        (const __half*)p_a2h, (const __half*)p_wh, CC, CC / BK, nullptr, out);
}

// round 4
// speedup vs baseline: 4.3256x; 1.0090x over previous
#include <cuda_runtime.h>
#include <cuda_fp16.h>
#include <mma.h>
#include <cstdint>

using namespace nvcuda;

#define NN 8192
#define CC 256

// ---------------------------------------------------------------------------
// Scratch (__device__ globals; allocation-free rule)
// ---------------------------------------------------------------------------
__device__ float  g_s[NN];                       // d^{-1/2}
__device__ __half g_adjh[(size_t)NN * NN];       // fp16(adj)
__device__ __half g_xsh[NN * CC];                // fp16(s_j * x[j][n])  [K][N]
__device__ __half g_a2h[NN * CC];                // fp16(s_i*(t + s_i*x)) [M][K]
__device__ __half g_wh[CC * CC];                 // fp16(w)  [K][N]

// ---------------------------------------------------------------------------
__device__ __forceinline__ uint32_t smem_u32(const void* p) {
    uint32_t a;
    asm("{ .reg .u64 t; cvta.to.shared.u64 t, %1; cvt.u32.u64 %0, t; }" : "=r"(a) : "l"(p));
    return a;
}
__device__ __forceinline__ void cpa16(uint32_t s, const void* g) {
    asm volatile("cp.async.cg.shared.global [%0], [%1], 16;" :: "r"(s), "l"(g));
}
#define CP_COMMIT() asm volatile("cp.async.commit_group;" ::: "memory")
#define CP_WAIT_2() asm volatile("cp.async.wait_group 2;" ::: "memory")

// ---------------------------------------------------------------------------
// Kernel 1: fused rowsum + f32->fp16 convert of adj.
// ---------------------------------------------------------------------------
__global__ void rowsum_convert_kernel(const float* __restrict__ adj) {
    const int row = blockIdx.x * blockDim.y + threadIdx.y;
    const float4* p = reinterpret_cast<const float4*>(adj + (size_t)row * NN);
    uint2* hout = reinterpret_cast<uint2*>(g_adjh + (size_t)row * NN);
    float sum = 0.0f;
#pragma unroll 4
    for (int i = threadIdx.x; i < NN / 4; i += 32) {
        float4 v = p[i];
        sum += (v.x + v.y) + (v.z + v.w);
        __half2 h0 = __floats2half2_rn(v.x, v.y);
        __half2 h1 = __floats2half2_rn(v.z, v.w);
        uint2 u;
        u.x = *reinterpret_cast<uint32_t*>(&h0);
        u.y = *reinterpret_cast<uint32_t*>(&h1);
        hout[i] = u;
    }
#pragma unroll
    for (int o = 16; o > 0; o >>= 1) sum += __shfl_xor_sync(0xffffffffu, sum, o);
    if (threadIdx.x == 0) g_s[row] = rsqrtf(sum + 1.0f);
}

// ---------------------------------------------------------------------------
__global__ void prep_xs_kernel(const float* __restrict__ x) {
    const int idx = blockIdx.x * 256 + threadIdx.x;   // over NN*CC/4 float4s
    const int row = idx >> 6;                          // CC/4 = 64 per row
    const float s = g_s[row];
    float4 v = reinterpret_cast<const float4*>(x)[idx];
    __half2 h0 = __floats2half2_rn(s * v.x, s * v.y);
    __half2 h1 = __floats2half2_rn(s * v.z, s * v.w);
    uint2 u;
    u.x = *reinterpret_cast<uint32_t*>(&h0);
    u.y = *reinterpret_cast<uint32_t*>(&h1);
    reinterpret_cast<uint2*>(g_xsh)[idx] = u;
}

__global__ void prep_w_kernel(const float* __restrict__ w) {
    const int idx = blockIdx.x * 256 + threadIdx.x;   // over CC*CC/4 float4s
    float4 v = reinterpret_cast<const float4*>(w)[idx];
    __half2 h0 = __floats2half2_rn(v.x, v.y);
    __half2 h1 = __floats2half2_rn(v.z, v.w);
    uint2 u;
    u.x = *reinterpret_cast<uint32_t*>(&h0);
    u.y = *reinterpret_cast<uint32_t*>(&h1);
    reinterpret_cast<uint2*>(g_wh)[idx] = u;
}

// ---------------------------------------------------------------------------
// fp16 WMMA GEMM, 4-stage cp.async pipeline, single barrier per K-iter,
// register double-buffered fragments.
//   MODE 0: epilogue writes g_a2h = fp16( s_i * (D + s_i * x) )
//   MODE 1: epilogue writes out  = ELU(D)  (f32)
// 256 threads = 8 warps as 4(M) x 2(N); warp tile 32x64.
// ---------------------------------------------------------------------------
constexpr int BM = 128, BN = 128, BK = 64, STAGES = 4;
constexpr int APAD = 72;                   // A smem row stride (halves)
constexpr int BPAD = 136;                  // B smem row stride (halves)
constexpr int A_HALVES = BM * APAD;        // 9216
constexpr int B_HALVES = BK * BPAD;        // 8704
constexpr int STAGE_BYTES = (A_HALVES + B_HALVES) * 2;   // 35840
constexpr int SMEM_BYTES = STAGES * STAGE_BYTES;          // 143360

template <int MODE>
__global__ __launch_bounds__(256, 1)
void gemm_fp16(const __half* __restrict__ A, const __half* __restrict__ B,
               int kA, int k_iters,
               const float* __restrict__ xin, float* __restrict__ outp) {
    extern __shared__ char smem[];
    const uint32_t sb = smem_u32(smem);
    const int tid = threadIdx.x;
    const int warp = tid >> 5;
    const int wm = warp & 3;     // 0..3 along M
    const int wn = warp >> 2;    // 0..1 along N
    const int m0 = blockIdx.y * BM;
    const int n0 = blockIdx.x * BN;

    // precomputed per-thread load coordinates
    const int arr = tid >> 3, arc = (tid & 7) * 8;          // A: 128r x 8 chunks
    const int brr = tid >> 4, brc = (tid & 15) * 8;         // B: 64r x 16 chunks
    const __half* gA = A + (size_t)(m0 + arr) * kA + arc;   // +32 rows per r-rep
    const __half* gB = B + (size_t)brr * CC + n0 + brc;     // +16 rows per r-rep
    const uint32_t sAo = (arr * APAD + arc) * 2;
    const uint32_t sBo = A_HALVES * 2 + (brr * BPAD + brc) * 2;

    wmma::fragment<wmma::accumulator, 16, 16, 16, float> acc[2][4];
#pragma unroll
    for (int i = 0; i < 2; i++)
#pragma unroll
        for (int j = 0; j < 4; j++) wmma::fill_fragment(acc[i][j], 0.0f);

    auto load_stage = [&](int kt, int s) {
        const uint32_t st = sb + s * STAGE_BYTES;
        const __half* a = gA + kt * BK;
        const __half* b = gB + (size_t)kt * BK * CC;
#pragma unroll
        for (int r = 0; r < 4; r++)
            cpa16(st + sAo + r * (32 * APAD * 2), a + (size_t)(r * 32) * kA);
#pragma unroll
        for (int r = 0; r < 4; r++)
            cpa16(st + sBo + r * (16 * BPAD * 2), b + (size_t)(r * 16) * CC);
    };

    // prologue: stages 0..2
#pragma unroll
    for (int s = 0; s < STAGES - 1; s++) {
        if (s < k_iters) load_stage(s, s);
        CP_COMMIT();
    }

    for (int kt = 0; kt < k_iters; kt++) {
        CP_WAIT_2();
        __syncthreads();   // single barrier: protects slot (kt-1)&3 rewrite below

        const int nk = kt + STAGES - 1;
        if (nk < k_iters) load_stage(nk, nk & 3);
        CP_COMMIT();

        const __half* Ap = reinterpret_cast<const __half*>(smem + (kt & 3) * STAGE_BYTES);
        const __half* Bp = Ap + A_HALVES;

        // register double-buffered fragment pipeline over 4 k-steps
        wmma::fragment<wmma::matrix_a, 16, 16, 16, __half, wmma::row_major> af[2][2];
        wmma::fragment<wmma::matrix_b, 16, 16, 16, __half, wmma::row_major> bf[2][4];
#pragma unroll
        for (int i = 0; i < 2; i++)
            wmma::load_matrix_sync(af[0][i], Ap + (wm * 32 + i * 16) * APAD, APAD);
#pragma unroll
        for (int j = 0; j < 4; j++)
            wmma::load_matrix_sync(bf[0][j], Bp + wn * 64 + j * 16, BPAD);

#pragma unroll
        for (int ks = 0; ks < 4; ks++) {
            const int cu = ks & 1, nx = cu ^ 1;
            if (ks < 3) {
#pragma unroll
                for (int i = 0; i < 2; i++)
                    wmma::load_matrix_sync(af[nx][i],
                        Ap + (wm * 32 + i * 16) * APAD + (ks + 1) * 16, APAD);
#pragma unroll
                for (int j = 0; j < 4; j++)
                    wmma::load_matrix_sync(bf[nx][j],
                        Bp + ((ks + 1) * 16) * BPAD + wn * 64 + j * 16, BPAD);
            }
#pragma unroll
            for (int i = 0; i < 2; i++)
#pragma unroll
                for (int j = 0; j < 4; j++)
                    wmma::mma_sync(acc[i][j], af[cu][i], bf[cu][j], acc[i][j]);
        }
    }
    __syncthreads();   // all MMA smem reads done before staging reuse

    // ---- epilogue: stage accumulators to smem (f32), then fused writeback ----
    float* stg = reinterpret_cast<float*>(smem);   // 128 x 132
#pragma unroll
    for (int i = 0; i < 2; i++)
#pragma unroll
        for (int j = 0; j < 4; j++)
            wmma::store_matrix_sync(stg + (wm * 32 + i * 16) * 132 + wn * 64 + j * 16,
                                    acc[i][j], 132, wmma::mem_row_major);
    __syncthreads();

    const int r = tid >> 1;             // 0..127
    const int c0 = (tid & 1) * 64;      // 0 or 64
    const int grow = m0 + r;
    float sA = 0.0f;
    if (MODE == 0) sA = g_s[grow];
#pragma unroll
    for (int c = 0; c < 64; c += 4) {
        float4 v = *reinterpret_cast<const float4*>(stg + r * 132 + c0 + c);
        const int gcol = n0 + c0 + c;
        if (MODE == 0) {
            const float4 xv = *reinterpret_cast<const float4*>(xin + (size_t)grow * CC + gcol);
            __half2 h0 = __floats2half2_rn(sA * (v.x + sA * xv.x), sA * (v.y + sA * xv.y));
            __half2 h1 = __floats2half2_rn(sA * (v.z + sA * xv.z), sA * (v.w + sA * xv.w));
            uint2 u;
            u.x = *reinterpret_cast<uint32_t*>(&h0);
            u.y = *reinterpret_cast<uint32_t*>(&h1);
            *reinterpret_cast<uint2*>(&g_a2h[(size_t)grow * CC + gcol]) = u;
        } else {
            v.x = (v.x > 0.0f) ? v.x : expm1f(v.x);
            v.y = (v.y > 0.0f) ? v.y : expm1f(v.y);
            v.z = (v.z > 0.0f) ? v.z : expm1f(v.z);
            v.w = (v.w > 0.0f) ? v.w : expm1f(v.w);
            *reinterpret_cast<float4*>(&outp[(size_t)grow * CC + gcol]) = v;
        }
    }
}

// ---------------------------------------------------------------------------
extern "C" void kernel_launch(void* const* d_in, const int* in_sizes, int n_in,
                              void* d_out, int out_size) {
    const float *x = nullptr, *adj = nullptr, *w = nullptr;
    for (int i = 0; i < n_in; i++) {
        if (in_sizes[i] == NN * NN) adj = (const float*)d_in[i];
        else if (in_sizes[i] == NN * CC) x = (const float*)d_in[i];
        else if (in_sizes[i] == CC * CC) w = (const float*)d_in[i];
    }
    float* out = (float*)d_out;

    void *p_adjh = nullptr, *p_xsh = nullptr, *p_a2h = nullptr, *p_wh = nullptr;
    cudaGetSymbolAddress(&p_adjh, g_adjh);
    cudaGetSymbolAddress(&p_xsh, g_xsh);
    cudaGetSymbolAddress(&p_a2h, g_a2h);
    cudaGetSymbolAddress(&p_wh, g_wh);

    cudaFuncSetAttribute(gemm_fp16<0>, cudaFuncAttributeMaxDynamicSharedMemorySize, SMEM_BYTES);
    cudaFuncSetAttribute(gemm_fp16<1>, cudaFuncAttributeMaxDynamicSharedMemorySize, SMEM_BYTES);

    rowsum_convert_kernel<<<NN / 8, dim3(32, 8)>>>(adj);
    prep_xs_kernel<<<NN * CC / 4 / 256, 256>>>(x);
    prep_w_kernel<<<CC * CC / 4 / 256, 256>>>(w);
    // grid: blockIdx.x = N tile (2, fast) so the pair sharing an adj row-tile
    // is co-resident -> L2 dedups the A read.
    gemm_fp16<0><<<dim3(2, 64), 256, SMEM_BYTES>>>(
        (const __half*)p_adjh, (const __half*)p_xsh, NN, NN / BK, x, nullptr);
    gemm_fp16<1><<<dim3(2, 64), 256, SMEM_BYTES>>>(
        (const __half*)p_a2h, (const __half*)p_wh, CC, CC / BK, nullptr, out);
}